// round 8
// baseline (speedup 1.0000x reference)
#include <cuda_runtime.h>
#include <cstdint>

#define N_POINTS   65536
#define N_ANCHORS  1024
#define MAX_PTS    512
#define NB         32                  // bins per axis
#define NBINS      (NB * NB)           // 1024
#define INV_S      0.32f               // 1 / (100/32)
#define CAP        256                 // max points per bin (actual max ~95)
#define CAND_CAP   320                 // max candidates per anchor (actual max ~230)
#define NCTA       1024
#define NTHR       128
#define PTS_PER_CTA (N_POINTS / NCTA)  // 64

// ---- scratch (device globals; no allocs allowed) ----
__device__ int    g_fill[NBINS];
__device__ float4 g_binned[NBINS * CAP];   // x, y, z, __int_as_float(orig_idx)
__device__ int    g_bar_cnt = 0;           // returns to 0 after each barrier
__device__ volatile int g_bar_gen = 0;     // monotonic generation (sense)

__device__ __forceinline__ int clamp31(int v) {
    return v < 0 ? 0 : (v > NB - 1 ? NB - 1 : v);
}
__device__ __forceinline__ int bin_x(float x) { return clamp31((int)floorf(x * INV_S)); }
__device__ __forceinline__ int bin_y(float y) { return clamp31((int)floorf(y * INV_S)); }

// Sense-reversing grid barrier. Safe because all NCTA CTAs are co-resident
// (guaranteed by __launch_bounds__(128,8) occupancy + host-side check).
// Generation counter is monotonic, so state is valid across graph replays.
__device__ __forceinline__ void grid_barrier() {
    __syncthreads();
    if (threadIdx.x == 0) {
        int my = g_bar_gen;                      // read sense BEFORE arriving
        __threadfence();                         // publish prior writes
        if (atomicAdd(&g_bar_cnt, 1) == NCTA - 1) {
            g_bar_cnt = 0;                       // reset for next barrier
            __threadfence();
            g_bar_gen = my + 1;                  // release
        } else {
            while (g_bar_gen == my) __nanosleep(64);
        }
        __threadfence();                         // acquire
    }
    __syncthreads();
}

// ================= fused single-launch kernel =================
__global__ void __launch_bounds__(NTHR, 8)
fused_kernel(const float* __restrict__ points,
             const float* __restrict__ anchors,
             float* __restrict__ out)
{
    __shared__ float4 s_cand[CAND_CAP];
    __shared__ int    s_idx[CAND_CAP];
    __shared__ int    s_cnt;

    const int tid = threadIdx.x;
    const int cta = blockIdx.x;

    // ---- phase 0: zero bin counters (CTA a owns bin a) ----
    if (tid == 0) { g_fill[cta] = 0; s_cnt = 0; }
    grid_barrier();

    // ---- phase 1: scatter (CTA a owns points [a*64, (a+1)*64)) ----
    if (tid < PTS_PER_CTA) {
        const int p = cta * PTS_PER_CTA + tid;
        float x = points[3 * p], y = points[3 * p + 1], z = points[3 * p + 2];
        int b = bin_y(y) * NB + bin_x(x);
        int slot = atomicAdd(&g_fill[b], 1);
        g_binned[b * CAP + slot] = make_float4(x, y, z, __int_as_float(p));
    }
    grid_barrier();

    // ---- phase 2: group (CTA a owns anchor a) ----
    const int a = cta;
    const float cx = anchors[a * 6 + 0];
    const float cy = anchors[a * 6 + 1];
    const float hw = anchors[a * 6 + 3] * 0.5f;
    const float hl = anchors[a * 6 + 4] * 0.5f;
    const float h  = anchors[a * 6 + 5];
    const float lox = cx - hw, hix = cx + hw;
    const float loy = cy - hl, hiy = cy + hl;

    // candidate bins (same floor/clamp expression as binning -> never misses);
    // a box side <= 5.0 units = 1.6 bins overlaps at most 3 bins per axis
    const int bx0 = bin_x(lox), bx1 = bin_x(hix);
    const int by0 = bin_y(loy), by1 = bin_y(hiy);

    // prefetch all (<=9) bin fill counts upfront: MLP=9 instead of serial chain
    int fills[9];
    #pragma unroll
    for (int k = 0; k < 9; k++) {
        int by = by0 + k / 3, bx = bx0 + k % 3;
        fills[k] = (by <= by1 && bx <= bx1) ? g_fill[by * NB + bx] : 0;
    }

    #pragma unroll
    for (int k = 0; k < 9; k++) {
        int by = by0 + k / 3, bx = bx0 + k % 3;
        if (by > by1 || bx > bx1) continue;
        const int fill = fills[k];
        const float4* bp = &g_binned[(by * NB + bx) * CAP];
        for (int i = tid; i < fill; i += NTHR) {
            float4 p = bp[i];
            if (p.x >= lox && p.x <= hix &&
                p.y >= loy && p.y <= hiy &&
                p.z >= 0.0f && p.z <= h) {
                int pos = atomicAdd(&s_cnt, 1);
                if (pos < CAND_CAP) {
                    s_cand[pos] = p;
                    s_idx[pos]  = __float_as_int(p.w);
                }
            }
        }
    }
    __syncthreads();

    const int total = s_cnt;
    const int c = total < CAND_CAP ? total : CAND_CAP;

    float* oa = out + (size_t)a * (MAX_PTS * 3);

    // rank by original index (ranks form a permutation of 0..c-1,
    // so ranked writes exactly tile positions [0, c))
    for (int i = tid; i < c; i += NTHR) {
        float4 e = s_cand[i];
        int ei = s_idx[i];
        int r = 0;
        for (int j = 0; j < c; j++)
            r += (s_idx[j] < ei);               // uniform smem broadcast
        float* o = oa + (size_t)r * 3;
        o[0] = e.x - cx;
        o[1] = e.y - cy;
        o[2] = e.z;
    }

    // tail-only zero fill: floats [c*3, 1536)
    const int start = c * 3;
    const int a4 = (start + 3) & ~3;
    for (int k = start + tid; k < a4; k += NTHR)
        oa[k] = 0.0f;
    float4* o4 = (float4*)oa;
    for (int i = (a4 >> 2) + tid; i < MAX_PTS * 3 / 4; i += NTHR)
        o4[i] = make_float4(0.f, 0.f, 0.f, 0.f);

    if (tid == 0)
        out[(size_t)N_ANCHORS * (MAX_PTS * 3) + a] = (float)total;
}

// ================= fallback 3-kernel path (no co-residency needed) ==========
__global__ void zero_kernel() { g_fill[threadIdx.x] = 0; }

__global__ void __launch_bounds__(256)
scatter_kernel(const float* __restrict__ points)
{
    const int t    = blockIdx.x * blockDim.x + threadIdx.x;
    const int base = t * 4;
    const float4* p4 = (const float4*)points;
    const int f4 = (base >> 2) * 3;
    float4 A = p4[f4 + 0];
    float4 B = p4[f4 + 1];
    float4 C = p4[f4 + 2];
    float x[4] = {A.x, A.w, B.z, C.y};
    float y[4] = {A.y, B.x, B.w, C.z};
    float z[4] = {A.z, B.y, C.x, C.w};
    int b[4], slot[4];
    #pragma unroll
    for (int k = 0; k < 4; k++) b[k] = bin_y(y[k]) * NB + bin_x(x[k]);
    #pragma unroll
    for (int k = 0; k < 4; k++) slot[k] = atomicAdd(&g_fill[b[k]], 1);
    #pragma unroll
    for (int k = 0; k < 4; k++)
        g_binned[b[k] * CAP + slot[k]] =
            make_float4(x[k], y[k], z[k], __int_as_float(base + k));
}

__global__ void __launch_bounds__(128)
group_kernel(const float* __restrict__ anchors, float* __restrict__ out)
{
    __shared__ float4 s_cand[CAND_CAP];
    __shared__ int    s_idx[CAND_CAP];
    __shared__ int s_cnt;
    const int a = blockIdx.x, tid = threadIdx.x;
    const float cx = anchors[a * 6 + 0];
    const float cy = anchors[a * 6 + 1];
    const float hw = anchors[a * 6 + 3] * 0.5f;
    const float hl = anchors[a * 6 + 4] * 0.5f;
    const float h  = anchors[a * 6 + 5];
    const float lox = cx - hw, hix = cx + hw;
    const float loy = cy - hl, hiy = cy + hl;
    if (tid == 0) s_cnt = 0;
    __syncthreads();
    const int bx0 = bin_x(lox), bx1 = bin_x(hix);
    const int by0 = bin_y(loy), by1 = bin_y(hiy);
    int fills[9];
    #pragma unroll
    for (int k = 0; k < 9; k++) {
        int by = by0 + k / 3, bx = bx0 + k % 3;
        fills[k] = (by <= by1 && bx <= bx1) ? g_fill[by * NB + bx] : 0;
    }
    #pragma unroll
    for (int k = 0; k < 9; k++) {
        int by = by0 + k / 3, bx = bx0 + k % 3;
        if (by > by1 || bx > bx1) continue;
        const float4* bp = &g_binned[(by * NB + bx) * CAP];
        for (int i = tid; i < fills[k]; i += 128) {
            float4 p = bp[i];
            if (p.x >= lox && p.x <= hix && p.y >= loy && p.y <= hiy &&
                p.z >= 0.0f && p.z <= h) {
                int pos = atomicAdd(&s_cnt, 1);
                if (pos < CAND_CAP) { s_cand[pos] = p; s_idx[pos] = __float_as_int(p.w); }
            }
        }
    }
    __syncthreads();
    const int total = s_cnt;
    const int c = total < CAND_CAP ? total : CAND_CAP;
    float* oa = out + (size_t)a * (MAX_PTS * 3);
    for (int i = tid; i < c; i += 128) {
        float4 e = s_cand[i];
        int ei = s_idx[i], r = 0;
        for (int j = 0; j < c; j++) r += (s_idx[j] < ei);
        float* o = oa + (size_t)r * 3;
        o[0] = e.x - cx; o[1] = e.y - cy; o[2] = e.z;
    }
    const int start = c * 3;
    const int a4 = (start + 3) & ~3;
    for (int k = start + tid; k < a4; k += 128) oa[k] = 0.0f;
    float4* o4 = (float4*)oa;
    for (int i = (a4 >> 2) + tid; i < MAX_PTS * 3 / 4; i += 128)
        o4[i] = make_float4(0.f, 0.f, 0.f, 0.f);
    if (tid == 0)
        out[(size_t)N_ANCHORS * (MAX_PTS * 3) + a] = (float)total;
}

extern "C" void kernel_launch(void* const* d_in, const int* in_sizes, int n_in,
                              void* d_out, int out_size)
{
    (void)in_sizes; (void)n_in; (void)out_size;
    const float* points  = (const float*)d_in[0];
    const float* anchors = (const float*)d_in[1];
    float* out = (float*)d_out;

    int dev = 0, nsm = 0, occ = 0;
    cudaGetDevice(&dev);
    cudaDeviceGetAttribute(&nsm, cudaDevAttrMultiProcessorCount, dev);
    cudaOccupancyMaxActiveBlocksPerMultiprocessor(&occ, fused_kernel, NTHR, 0);

    if ((long)occ * nsm >= NCTA) {
        fused_kernel<<<NCTA, NTHR>>>(points, anchors, out);
    } else {
        zero_kernel   <<<1, NBINS>>>();
        scatter_kernel<<<N_POINTS / (256 * 4), 256>>>(points);
        group_kernel  <<<N_ANCHORS, 128>>>(anchors, out);
    }
}